// round 15
// baseline (speedup 1.0000x reference)
#include <cuda_runtime.h>
#include <math.h>

#define NFULL 50000
#define NPOOL 12500
#define EFULL 600000
#define EPOOL 150000
#define DD    128
#define NBF   ((NFULL + 1023) / 1024)   // 49
#define NBP   ((NPOOL + 1023) / 1024)   // 13

// ---------------- device scratch (no allocation allowed) ----------------
__device__ float d_ypool[NPOOL * DD];
__device__ float d_h[NPOOL * DD];
__device__ float d_y[NFULL * DD];
__device__ float d_xf1[NFULL * DD];
__device__ int   d_degp[NPOOL];
__device__ int   d_degf[NFULL];
__device__ int   d_offf[NFULL + 1];
__device__ int   d_offp[NPOOL + 1];
__device__ int   d_curfA[NFULL];   // front cursor (kept edges)
__device__ int   d_curfB[NFULL];   // back cursor (unkept edges)
__device__ int   d_curp[NPOOL];
__device__ int   d_csrf[EFULL];
__device__ int   d_csrp[EPOOL];
__device__ int   d_mask[NFULL];
__device__ int   d_sumsF[64];
__device__ int   d_sumsP[64];

// ---------------- packed f32x2 asm ----------------
#define FMA2(acc, a, b) \
    asm("fma.rn.f32x2 %0, %1, %2, %0;" : "+l"(acc) : "l"(a), "l"(b))
#define PACK2(out, lo, hi) \
    asm("mov.b64 %0, {%1, %2};" : "=l"(out) : "f"(lo), "f"(hi))
#define UNPACK2(lo, hi, in) \
    asm("mov.b64 {%0, %1}, %2;" : "=f"(lo), "=f"(hi) : "l"(in))

// ---------------- degree kernels (4-wide MLP) ----------------
// full graph: blockIdx.y==0 -> degrees, blockIdx.y==1 -> kept mask
__global__ __launch_bounds__(256) void degF_mask_kernel(
    const int* __restrict__ dst, int E, int* __restrict__ deg,
    const int* __restrict__ remap, int nP, int* __restrict__ mask)
{
    int t = blockIdx.x * blockDim.x + threadIdx.x;
    int S = gridDim.x * blockDim.x;
    if (blockIdx.y == 0) {
        for (int b = t; b < E; b += 4 * S) {
            int i1 = b + S, i2 = b + 2 * S, i3 = b + 3 * S;
            int d0 = dst[b];
            atomicAdd(&deg[d0], 1);
            if (i1 < E) { int d1 = dst[i1]; atomicAdd(&deg[d1], 1); }
            if (i2 < E) { int d2 = dst[i2]; atomicAdd(&deg[d2], 1); }
            if (i3 < E) { int d3 = dst[i3]; atomicAdd(&deg[d3], 1); }
        }
    } else {
        for (int i = t; i < nP; i += S) mask[remap[i]] = 1;
    }
}

__global__ __launch_bounds__(256) void degP_kernel(
    const int* __restrict__ dst, int E, int* __restrict__ deg)
{
    int t = blockIdx.x * blockDim.x + threadIdx.x;
    int S = gridDim.x * blockDim.x;
    for (int b = t; b < E; b += 4 * S) {
        int i1 = b + S, i2 = b + 2 * S, i3 = b + 3 * S;
        int d0 = dst[b];
        atomicAdd(&deg[d0], 1);
        if (i1 < E) { int d1 = dst[i1]; atomicAdd(&deg[d1], 1); }
        if (i2 < E) { int d2 = dst[i2]; atomicAdd(&deg[d2], 1); }
        if (i3 < E) { int d3 = dst[i3]; atomicAdd(&deg[d3], 1); }
    }
}

// ---- 2-kernel parallel exclusive scan ----
__global__ __launch_bounds__(1024) void scan_p1(
    const int* __restrict__ deg, int n, int* __restrict__ sums)
{
    int base = blockIdx.x * 1024;
    if (base >= n) return;
    int i = base + threadIdx.x;
    int v = (i < n) ? deg[i] : 0;
    __shared__ int ws[32];
    int lane = threadIdx.x & 31, wid = threadIdx.x >> 5;
#pragma unroll
    for (int d = 16; d > 0; d >>= 1) v += __shfl_down_sync(0xffffffffu, v, d);
    if (lane == 0) ws[wid] = v;
    __syncthreads();
    if (wid == 0) {
        int t = ws[lane];
#pragma unroll
        for (int d = 16; d > 0; d >>= 1) t += __shfl_down_sync(0xffffffffu, t, d);
        if (lane == 0) sums[blockIdx.x] = t;
    }
}

// each block reduces preceding block-sums itself, scans its 1024 elements,
// writes off[i], CSR cursor(s), and off[n] at the tail.
__global__ __launch_bounds__(1024) void scan_p3(
    const int* __restrict__ deg, int n, const int* __restrict__ sums,
    int* __restrict__ off, int* __restrict__ curA, int* __restrict__ curB)
{
    int base = blockIdx.x * 1024;
    if (base >= n) return;

    __shared__ int ws[32];
    __shared__ int red2[2];
    __shared__ int sumbase_s;
    int tid = threadIdx.x;
    int lane = tid & 31, wid = tid >> 5;

    if (tid < 64) {
        int v = (tid < blockIdx.x) ? sums[tid] : 0;
#pragma unroll
        for (int d = 16; d > 0; d >>= 1) v += __shfl_down_sync(0xffffffffu, v, d);
        if (lane == 0) red2[wid] = v;
    }
    __syncthreads();
    if (tid == 0) sumbase_s = red2[0] + red2[1];
    __syncthreads();

    int i = base + tid;
    int v = (i < n) ? deg[i] : 0;
    int x = v;
#pragma unroll
    for (int d = 1; d < 32; d <<= 1) {
        int t = __shfl_up_sync(0xffffffffu, x, d);
        if (lane >= d) x += t;
    }
    if (lane == 31) ws[wid] = x;
    __syncthreads();
    if (wid == 0) {
        int w = ws[lane];
#pragma unroll
        for (int d = 1; d < 32; d <<= 1) {
            int t = __shfl_up_sync(0xffffffffu, w, d);
            if (lane >= d) w += t;
        }
        ws[lane] = w;
    }
    __syncthreads();
    int excl = (x - v) + (wid > 0 ? ws[wid - 1] : 0) + sumbase_s;
    if (i < n) {
        off[i]  = excl;
        curA[i] = excl;                    // front cursor
        if (curB) curB[i] = excl + v;      // back cursor (full graph only)
        if (i == n - 1) off[n] = excl + v;
    }
}

// ---------------- CSR build, 4-wide MLP ----------------
// full graph: kept-source edges compacted to FRONT (bit31 set); unkept from back.
__global__ __launch_bounds__(256) void csrF_kernel(
    const int* __restrict__ src, const int* __restrict__ dst, int E,
    int* __restrict__ curA, int* __restrict__ curB, int* __restrict__ csr,
    const int* __restrict__ mask)
{
    int t = blockIdx.x * blockDim.x + threadIdx.x;
    int S = gridDim.x * blockDim.x;
    for (int b = t; b < E; b += 4 * S) {
        int i1 = b + S, i2 = b + 2 * S, i3 = b + 3 * S;
        bool v1 = i1 < E, v2 = i2 < E, v3 = i3 < E;
        int d0 = dst[b],            s0 = src[b];
        int d1 = v1 ? dst[i1] : 0,  s1 = v1 ? src[i1] : 0;
        int d2 = v2 ? dst[i2] : 0,  s2 = v2 ? src[i2] : 0;
        int d3 = v3 ? dst[i3] : 0,  s3 = v3 ? src[i3] : 0;
        int m0 = mask[s0];
        int m1 = v1 ? mask[s1] : 0;
        int m2 = v2 ? mask[s2] : 0;
        int m3 = v3 ? mask[s3] : 0;
        int p0 = m0 ? atomicAdd(&curA[d0], 1) : (atomicSub(&curB[d0], 1) - 1);
        int p1 = v1 ? (m1 ? atomicAdd(&curA[d1], 1) : (atomicSub(&curB[d1], 1) - 1)) : 0;
        int p2 = v2 ? (m2 ? atomicAdd(&curA[d2], 1) : (atomicSub(&curB[d2], 1) - 1)) : 0;
        int p3 = v3 ? (m3 ? atomicAdd(&curA[d3], 1) : (atomicSub(&curB[d3], 1) - 1)) : 0;
        csr[p0] = s0 | (m0 ? 0x80000000 : 0);
        if (v1) csr[p1] = s1 | (m1 ? 0x80000000 : 0);
        if (v2) csr[p2] = s2 | (m2 ? 0x80000000 : 0);
        if (v3) csr[p3] = s3 | (m3 ? 0x80000000 : 0);
    }
}

__global__ __launch_bounds__(256) void csrP_kernel(
    const int* __restrict__ src, const int* __restrict__ dst, int E,
    int* __restrict__ curA, int* __restrict__ csr)
{
    int t = blockIdx.x * blockDim.x + threadIdx.x;
    int S = gridDim.x * blockDim.x;
    for (int b = t; b < E; b += 4 * S) {
        int i1 = b + S, i2 = b + 2 * S, i3 = b + 3 * S;
        bool v1 = i1 < E, v2 = i2 < E, v3 = i3 < E;
        int d0 = dst[b],           s0 = src[b];
        int d1 = v1 ? dst[i1] : 0, s1 = v1 ? src[i1] : 0;
        int d2 = v2 ? dst[i2] : 0, s2 = v2 ? src[i2] : 0;
        int d3 = v3 ? dst[i3] : 0, s3 = v3 ? src[i3] : 0;
        int p0 = atomicAdd(&curA[d0], 1);
        int p1 = v1 ? atomicAdd(&curA[d1], 1) : 0;
        int p2 = v2 ? atomicAdd(&curA[d2], 1) : 0;
        int p3 = v3 ? atomicAdd(&curA[d3], 1) : 0;
        csr[p0] = s0;
        if (v1) csr[p1] = s1;
        if (v2) csr[p2] = s2;
        if (v3) csr[p3] = s3;
    }
}

// ---------------- GEMM: y[node] = dinv[node] * (X[row] @ W), f32x2 packed ----------------
template <int REMAP>
__global__ __launch_bounds__(256) void gemm_kernel(
    const float* __restrict__ X, const float* __restrict__ W, int M,
    const int* __restrict__ off, const int* __restrict__ remap,
    float* __restrict__ y)
{
    __shared__ __align__(16) float AsT[32][66];
    __shared__ __align__(16) float Bs[32][128];
    int tid = threadIdx.x;
    int lane = tid & 31;
    int ty = tid >> 5;
    int rowBase = blockIdx.x * 64;

    unsigned long long acc[4][4];
#pragma unroll
    for (int rp = 0; rp < 4; rp++)
#pragma unroll
        for (int c = 0; c < 4; c++) acc[rp][c] = 0ull;

    for (int k0 = 0; k0 < 128; k0 += 32) {
#pragma unroll
        for (int s = 0; s < 2; s++) {
            int idx = tid * 2 + s;
            int r = idx >> 3;
            int c4 = idx & 7;
            float4 v = make_float4(0.f, 0.f, 0.f, 0.f);
            int grow = rowBase + r;
            if (grow < M) v = *(const float4*)(X + (size_t)grow * 128 + k0 + c4 * 4);
            AsT[c4 * 4 + 0][r] = v.x;
            AsT[c4 * 4 + 1][r] = v.y;
            AsT[c4 * 4 + 2][r] = v.z;
            AsT[c4 * 4 + 3][r] = v.w;
        }
#pragma unroll
        for (int s = 0; s < 4; s++) {
            int idx = tid * 4 + s;
            int r = idx >> 5;
            int c4 = idx & 31;
            *(float4*)&Bs[r][c4 * 4] = *(const float4*)(W + (size_t)(k0 + r) * 128 + c4 * 4);
        }
        __syncthreads();
#pragma unroll
        for (int k = 0; k < 32; k++) {
            unsigned long long a0 = *(const unsigned long long*)&AsT[k][ty * 8 + 0];
            unsigned long long a1 = *(const unsigned long long*)&AsT[k][ty * 8 + 2];
            unsigned long long a2 = *(const unsigned long long*)&AsT[k][ty * 8 + 4];
            unsigned long long a3 = *(const unsigned long long*)&AsT[k][ty * 8 + 6];
            float4 b = *(float4*)&Bs[k][lane * 4];
            unsigned long long bx, by, bz, bw;
            PACK2(bx, b.x, b.x);
            PACK2(by, b.y, b.y);
            PACK2(bz, b.z, b.z);
            PACK2(bw, b.w, b.w);
            FMA2(acc[0][0], a0, bx); FMA2(acc[0][1], a0, by);
            FMA2(acc[0][2], a0, bz); FMA2(acc[0][3], a0, bw);
            FMA2(acc[1][0], a1, bx); FMA2(acc[1][1], a1, by);
            FMA2(acc[1][2], a1, bz); FMA2(acc[1][3], a1, bw);
            FMA2(acc[2][0], a2, bx); FMA2(acc[2][1], a2, by);
            FMA2(acc[2][2], a2, bz); FMA2(acc[2][3], a2, bw);
            FMA2(acc[3][0], a3, bx); FMA2(acc[3][1], a3, by);
            FMA2(acc[3][2], a3, bz); FMA2(acc[3][3], a3, bw);
        }
        __syncthreads();
    }

#pragma unroll
    for (int rp = 0; rp < 4; rp++) {
        float lo0, hi0, lo1, hi1, lo2, hi2, lo3, hi3;
        UNPACK2(lo0, hi0, acc[rp][0]);
        UNPACK2(lo1, hi1, acc[rp][1]);
        UNPACK2(lo2, hi2, acc[rp][2]);
        UNPACK2(lo3, hi3, acc[rp][3]);
        int r0 = rowBase + ty * 8 + rp * 2;
        if (r0 < M) {
            int node = REMAP ? remap[r0] : r0;
            float s = rsqrtf((float)(off[node + 1] - off[node] + 1));
            float4 v = make_float4(lo0 * s, lo1 * s, lo2 * s, lo3 * s);
            *(float4*)(y + (size_t)node * 128 + lane * 4) = v;
        }
        if (r0 + 1 < M) {
            int node = REMAP ? remap[r0 + 1] : (r0 + 1);
            float s = rsqrtf((float)(off[node + 1] - off[node] + 1));
            float4 v = make_float4(hi0 * s, hi1 * s, hi2 * s, hi3 * s);
            *(float4*)(y + (size_t)node * 128 + lane * 4) = v;
        }
    }
}

// ---------------- fused gather + finalize ----------------
__device__ __forceinline__ float elu1(float x) {
    return x > 0.f ? x : expm1f(x);
}

template <int MODE>
__global__ __launch_bounds__(256) void gather_kernel(
    const int* __restrict__ off, const int* __restrict__ csr,
    const float* __restrict__ y, const float* __restrict__ b,
    float* __restrict__ out, int n, const int* __restrict__ mask)
{
    int lane = threadIdx.x & 31;
    int node = (blockIdx.x * blockDim.x + threadIdx.x) >> 5;
    if (node >= n) return;
    int e0 = __ldg(&off[node]);
    int e1 = __ldg(&off[node + 1]);
    const float* yl = y + lane * 4;

    float4 a0 = make_float4(0.f, 0.f, 0.f, 0.f);
    float4 a1 = make_float4(0.f, 0.f, 0.f, 0.f);
    float4 a2 = make_float4(0.f, 0.f, 0.f, 0.f);
    float4 a3 = make_float4(0.f, 0.f, 0.f, 0.f);

    bool selfOk = (MODE == 2) ? (__ldg(&mask[node]) != 0) : true;
    if (selfOk) a0 = *(const float4*)(yl + (size_t)node * 128);

    int e = e0;
    if (MODE == 2) {
        for (; e + 2 <= e1; e += 2) {
            int sA = __ldg(&csr[e]);
            int sB = __ldg(&csr[e + 1]);
            if (sA >= 0) goto done;
            {
                float4 vA = *(const float4*)(yl + (size_t)(sA & 0x7fffffff) * 128);
                a0.x += vA.x; a0.y += vA.y; a0.z += vA.z; a0.w += vA.w;
            }
            if (sB >= 0) goto done;
            {
                float4 vB = *(const float4*)(yl + (size_t)(sB & 0x7fffffff) * 128);
                a1.x += vB.x; a1.y += vB.y; a1.z += vB.z; a1.w += vB.w;
            }
        }
        if (e < e1) {
            int sA = __ldg(&csr[e]);
            if (sA < 0) {
                float4 vA = *(const float4*)(yl + (size_t)(sA & 0x7fffffff) * 128);
                a0.x += vA.x; a0.y += vA.y; a0.z += vA.z; a0.w += vA.w;
            }
        }
        done: ;
    } else {
        for (; e + 4 <= e1; e += 4) {
            int s0 = __ldg(&csr[e]);
            int s1 = __ldg(&csr[e + 1]);
            int s2 = __ldg(&csr[e + 2]);
            int s3 = __ldg(&csr[e + 3]);
            if (MODE == 1) {
                s0 &= 0x7fffffff; s1 &= 0x7fffffff;
                s2 &= 0x7fffffff; s3 &= 0x7fffffff;
            }
            float4 v0 = *(const float4*)(yl + (size_t)s0 * 128);
            float4 v1 = *(const float4*)(yl + (size_t)s1 * 128);
            float4 v2 = *(const float4*)(yl + (size_t)s2 * 128);
            float4 v3 = *(const float4*)(yl + (size_t)s3 * 128);
            a0.x += v0.x; a0.y += v0.y; a0.z += v0.z; a0.w += v0.w;
            a1.x += v1.x; a1.y += v1.y; a1.z += v1.z; a1.w += v1.w;
            a2.x += v2.x; a2.y += v2.y; a2.z += v2.z; a2.w += v2.w;
            a3.x += v3.x; a3.y += v3.y; a3.z += v3.z; a3.w += v3.w;
        }
        for (; e < e1; e++) {
            int s = __ldg(&csr[e]);
            if (MODE == 1) s &= 0x7fffffff;
            float4 v = *(const float4*)(yl + (size_t)s * 128);
            a0.x += v.x; a0.y += v.y; a0.z += v.z; a0.w += v.w;
        }
    }
    a0.x += a1.x + a2.x + a3.x;
    a0.y += a1.y + a2.y + a3.y;
    a0.z += a1.z + a2.z + a3.z;
    a0.w += a1.w + a2.w + a3.w;

    float s = rsqrtf((float)(e1 - e0 + 1));
    float4 bb = *(const float4*)(b + lane * 4);
    float4 o;
    o.x = elu1(fmaf(s, a0.x, bb.x));
    o.y = elu1(fmaf(s, a0.y, bb.y));
    o.z = elu1(fmaf(s, a0.z, bb.z));
    o.w = elu1(fmaf(s, a0.w, bb.w));
    *(float4*)(out + (size_t)node * 128 + lane * 4) = o;
}

// ---------------- launch (stream-parallel capture DAG) ----------------
extern "C" void kernel_launch(void* const* d_in, const int* in_sizes, int n_in,
                              void* d_out, int out_size)
{
    const int* ei   = (const int*)d_in[1];
    const float* px = (const float*)d_in[2];
    const int* pei  = (const int*)d_in[3];
    const int* up   = (const int*)d_in[4];
    const float* W0 = (const float*)d_in[5];
    const float* b0 = (const float*)d_in[6];
    const float* W1 = (const float*)d_in[7];
    const float* b1 = (const float*)d_in[8];
    const float* W2 = (const float*)d_in[9];
    const float* b2 = (const float*)d_in[10];
    float* out = (float*)d_out;

    int nf = in_sizes[0] / DD;
    int ef = in_sizes[1] / 2;
    int np = in_sizes[2] / DD;
    int ep = in_sizes[3] / 2;

    float *ypool, *h, *y, *xf1;
    int *degp, *degf, *offf, *offp, *curfA, *curfB, *curp;
    int *csrf, *csrp, *mask, *sumsF, *sumsP;
    cudaGetSymbolAddress((void**)&ypool, d_ypool);
    cudaGetSymbolAddress((void**)&h,     d_h);
    cudaGetSymbolAddress((void**)&y,     d_y);
    cudaGetSymbolAddress((void**)&xf1,   d_xf1);
    cudaGetSymbolAddress((void**)&degp,  d_degp);
    cudaGetSymbolAddress((void**)&degf,  d_degf);
    cudaGetSymbolAddress((void**)&offf,  d_offf);
    cudaGetSymbolAddress((void**)&offp,  d_offp);
    cudaGetSymbolAddress((void**)&curfA, d_curfA);
    cudaGetSymbolAddress((void**)&curfB, d_curfB);
    cudaGetSymbolAddress((void**)&curp,  d_curp);
    cudaGetSymbolAddress((void**)&csrf,  d_csrf);
    cudaGetSymbolAddress((void**)&csrp,  d_csrp);
    cudaGetSymbolAddress((void**)&mask,  d_mask);
    cudaGetSymbolAddress((void**)&sumsF, d_sumsF);
    cudaGetSymbolAddress((void**)&sumsP, d_sumsP);

    // lazily created host-side resources (no device memory); identical launch
    // sequence every call.
    static cudaStream_t s1 = nullptr, s2 = nullptr;
    static cudaEvent_t evRoot = nullptr, evScanF = nullptr, evCsrF = nullptr,
                       evCsrP = nullptr, evDone = nullptr;
    if (!s1) {
        cudaStreamCreateWithFlags(&s1, cudaStreamNonBlocking);
        cudaStreamCreateWithFlags(&s2, cudaStreamNonBlocking);
        cudaEventCreateWithFlags(&evRoot, cudaEventDisableTiming);
        cudaEventCreateWithFlags(&evScanF, cudaEventDisableTiming);
        cudaEventCreateWithFlags(&evCsrF, cudaEventDisableTiming);
        cudaEventCreateWithFlags(&evCsrP, cudaEventDisableTiming);
        cudaEventCreateWithFlags(&evDone, cudaEventDisableTiming);
    }

    const int T = 256;
    auto cdiv = [](int a, int b) { return (a + b - 1) / b; };

    // ---- fork side streams from the capturing (legacy) stream ----
    cudaEventRecord(evRoot, 0);
    cudaStreamWaitEvent(s1, evRoot, 0);
    cudaStreamWaitEvent(s2, evRoot, 0);

    // ---- stream 0: full-graph preprocessing chain ----
    cudaMemsetAsync(degf, 0, nf * sizeof(int), 0);
    degF_mask_kernel<<<dim3(cdiv(ef, T * 4), 2), T, 0, 0>>>(ei + ef, ef, degf, up, np, mask);
    scan_p1<<<NBF, 1024, 0, 0>>>(degf, nf, sumsF);
    scan_p3<<<NBF, 1024, 0, 0>>>(degf, nf, sumsF, offf, curfA, curfB);
    cudaEventRecord(evScanF, 0);
    csrF_kernel<<<cdiv(ef, T * 4), T, 0, 0>>>(ei, ei + ef, ef, curfA, curfB, csrf, mask);
    cudaEventRecord(evCsrF, 0);

    // ---- s1: pooled-graph preprocessing chain ----
    cudaMemsetAsync(degp, 0, np * sizeof(int), s1);
    degP_kernel<<<cdiv(ep, T * 4), T, 0, s1>>>(pei + ep, ep, degp);
    scan_p1<<<NBP, 1024, 0, s1>>>(degp, np, sumsP);
    scan_p3<<<NBP, 1024, 0, s1>>>(degp, np, sumsP, offp, curp, nullptr);
    csrP_kernel<<<cdiv(ep, T * 4), T, 0, s1>>>(pei, pei + ep, ep, curp, csrp);
    cudaEventRecord(evCsrP, s1);

    // ---- s2: conv compute chain (joins at true data dependencies) ----
    // gemm0 epilogue reads offp -> must wait for pooled scan+csr chain
    cudaStreamWaitEvent(s2, evCsrP, 0);
    gemm_kernel<0><<<cdiv(np, 64), 256, 0, s2>>>(px, W0, np, offp, nullptr, ypool);
    gather_kernel<0><<<cdiv(np * 32, T), T, 0, s2>>>(offp, csrp, ypool, b0, h, np, nullptr);
    cudaStreamWaitEvent(s2, evScanF, 0);
    gemm_kernel<1><<<cdiv(np, 64), 256, 0, s2>>>(h, W1, np, offf, up, y);
    cudaStreamWaitEvent(s2, evCsrF, 0);
    gather_kernel<2><<<cdiv(nf * 32, T), T, 0, s2>>>(offf, csrf, y, b1, xf1, nf, mask);
    gemm_kernel<0><<<cdiv(nf, 64), 256, 0, s2>>>(xf1, W2, nf, offf, nullptr, y);
    gather_kernel<1><<<cdiv(nf * 32, T), T, 0, s2>>>(offf, csrf, y, b2, out, nf, nullptr);
    cudaEventRecord(evDone, s2);

    // ---- join everything back into the capturing stream ----
    cudaStreamWaitEvent(0, evDone, 0);
}

// round 16
// speedup vs baseline: 1.0215x; 1.0215x over previous
#include <cuda_runtime.h>
#include <math.h>

#define NFULL 50000
#define NPOOL 12500
#define EFULL 600000
#define EPOOL 150000
#define DD    128
#define NBF   ((NFULL + 1023) / 1024)   // 49
#define NBP   ((NPOOL + 1023) / 1024)   // 13
#define MBW   ((NFULL + 31) / 32)       // mask bit-words

// ---------------- device scratch (no allocation allowed) ----------------
__device__ float d_ypool[NPOOL * DD];
__device__ float d_h[NPOOL * DD];
__device__ float d_y[NFULL * DD];
__device__ float d_xf1[NFULL * DD];
__device__ int   d_degp[NPOOL];
__device__ int   d_degf[NFULL];
__device__ int   d_offf[NFULL + 1];
__device__ int   d_offp[NPOOL + 1];
__device__ int   d_curfA[NFULL];   // front cursor (kept edges)
__device__ int   d_curfB[NFULL];   // back cursor (unkept edges)
__device__ int   d_curp[NPOOL];
__device__ int   d_csrf[EFULL];
__device__ int   d_csrp[EPOOL];
__device__ unsigned int d_maskbits[MBW];
__device__ int   d_sumsF[64];
__device__ int   d_sumsP[64];

// ---------------- packed f32x2 asm ----------------
#define FMA2(acc, a, b) \
    asm("fma.rn.f32x2 %0, %1, %2, %0;" : "+l"(acc) : "l"(a), "l"(b))
#define PACK2(out, lo, hi) \
    asm("mov.b64 %0, {%1, %2};" : "=l"(out) : "f"(lo), "f"(hi))
#define UNPACK2(lo, hi, in) \
    asm("mov.b64 {%0, %1}, %2;" : "=f"(lo), "=f"(hi) : "l"(in))

__device__ __forceinline__ int mask_test(const unsigned int* __restrict__ mb, int i) {
    return (__ldg(&mb[i >> 5]) >> (i & 31)) & 1;
}

// ---------------- degree + mask kernel (8-wide MLP) ----------------
// blockIdx.y: 0 = full-graph degrees, 1 = pooled degrees, 2 = mask bits
__global__ __launch_bounds__(256) void degmask_kernel(
    const int* __restrict__ dstF, int EF, int* __restrict__ degF,
    const int* __restrict__ dstP, int EP, int* __restrict__ degP,
    const int* __restrict__ remap, int nP, unsigned int* __restrict__ maskbits)
{
    int t = blockIdx.x * blockDim.x + threadIdx.x;
    int S = gridDim.x * blockDim.x;
    if (blockIdx.y == 0) {
        for (int b = t; b < EF; b += 8 * S) {
            int d[8]; bool v[8];
#pragma unroll
            for (int j = 0; j < 8; j++) {
                int i = b + j * S;
                v[j] = i < EF;
                d[j] = v[j] ? dstF[i] : 0;
            }
#pragma unroll
            for (int j = 0; j < 8; j++)
                if (v[j]) atomicAdd(&degF[d[j]], 1);
        }
    } else if (blockIdx.y == 1) {
        for (int b = t; b < EP; b += 8 * S) {
            int d[8]; bool v[8];
#pragma unroll
            for (int j = 0; j < 8; j++) {
                int i = b + j * S;
                v[j] = i < EP;
                d[j] = v[j] ? dstP[i] : 0;
            }
#pragma unroll
            for (int j = 0; j < 8; j++)
                if (v[j]) atomicAdd(&degP[d[j]], 1);
        }
    } else {
        for (int i = t; i < nP; i += S) {
            int node = remap[i];
            atomicOr(&maskbits[node >> 5], 1u << (node & 31));
        }
    }
}

// ---- 2-kernel parallel exclusive scan (both graphs batched via blockIdx.y) ----
__global__ __launch_bounds__(1024) void scan_p1(
    const int* __restrict__ degF, int nF, int* __restrict__ sumsF,
    const int* __restrict__ degP, int nP, int* __restrict__ sumsP)
{
    const int* deg = blockIdx.y ? degP : degF;
    int n = blockIdx.y ? nP : nF;
    int* sums = blockIdx.y ? sumsP : sumsF;
    int base = blockIdx.x * 1024;
    if (base >= n) return;
    int i = base + threadIdx.x;
    int v = (i < n) ? deg[i] : 0;
    __shared__ int ws[32];
    int lane = threadIdx.x & 31, wid = threadIdx.x >> 5;
#pragma unroll
    for (int d = 16; d > 0; d >>= 1) v += __shfl_down_sync(0xffffffffu, v, d);
    if (lane == 0) ws[wid] = v;
    __syncthreads();
    if (wid == 0) {
        int t = ws[lane];
#pragma unroll
        for (int d = 16; d > 0; d >>= 1) t += __shfl_down_sync(0xffffffffu, t, d);
        if (lane == 0) sums[blockIdx.x] = t;
    }
}

// each block reduces preceding block-sums itself, scans its 1024 elements,
// writes off[i], CSR cursor(s), and off[n] at the tail.
__global__ __launch_bounds__(1024) void scan_p3(
    const int* __restrict__ degF, int nF, const int* __restrict__ sumsF,
    int* __restrict__ offF, int* __restrict__ curAF, int* __restrict__ curBF,
    const int* __restrict__ degP, int nP, const int* __restrict__ sumsP,
    int* __restrict__ offP, int* __restrict__ curAP)
{
    const int* deg  = blockIdx.y ? degP  : degF;
    int n           = blockIdx.y ? nP    : nF;
    const int* sums = blockIdx.y ? sumsP : sumsF;
    int* off        = blockIdx.y ? offP  : offF;
    int* curA       = blockIdx.y ? curAP : curAF;
    int* curB       = blockIdx.y ? (int*)0 : curBF;
    int base = blockIdx.x * 1024;
    if (base >= n) return;

    __shared__ int ws[32];
    __shared__ int red2[2];
    __shared__ int sumbase_s;
    int tid = threadIdx.x;
    int lane = tid & 31, wid = tid >> 5;

    if (tid < 64) {
        int v = (tid < blockIdx.x) ? sums[tid] : 0;
#pragma unroll
        for (int d = 16; d > 0; d >>= 1) v += __shfl_down_sync(0xffffffffu, v, d);
        if (lane == 0) red2[wid] = v;
    }
    __syncthreads();
    if (tid == 0) sumbase_s = red2[0] + red2[1];
    __syncthreads();

    int i = base + tid;
    int v = (i < n) ? deg[i] : 0;
    int x = v;
#pragma unroll
    for (int d = 1; d < 32; d <<= 1) {
        int t = __shfl_up_sync(0xffffffffu, x, d);
        if (lane >= d) x += t;
    }
    if (lane == 31) ws[wid] = x;
    __syncthreads();
    if (wid == 0) {
        int w = ws[lane];
#pragma unroll
        for (int d = 1; d < 32; d <<= 1) {
            int t = __shfl_up_sync(0xffffffffu, w, d);
            if (lane >= d) w += t;
        }
        ws[lane] = w;
    }
    __syncthreads();
    int excl = (x - v) + (wid > 0 ? ws[wid - 1] : 0) + sumbase_s;
    if (i < n) {
        off[i]  = excl;
        curA[i] = excl;                    // front cursor
        if (curB) curB[i] = excl + v;      // back cursor (full graph only)
        if (i == n - 1) off[n] = excl + v;
    }
}

// ---------------- CSR build (batched, 8-wide MLP, bitmask) ----------------
// full graph: kept-source edges compacted to FRONT (bit31 set); unkept from back.
__global__ __launch_bounds__(256) void csr_kernel(
    const int* __restrict__ srcF, const int* __restrict__ dstF, int EF,
    int* __restrict__ curAF, int* __restrict__ curBF, int* __restrict__ csrF,
    const unsigned int* __restrict__ maskbits,
    const int* __restrict__ srcP, const int* __restrict__ dstP, int EP,
    int* __restrict__ curAP, int* __restrict__ csrP)
{
    int t = blockIdx.x * blockDim.x + threadIdx.x;
    int S = gridDim.x * blockDim.x;
    if (blockIdx.y == 0) {
        for (int b = t; b < EF; b += 8 * S) {
            int s[8], d[8], m[8], p[8]; bool v[8];
#pragma unroll
            for (int j = 0; j < 8; j++) {
                int i = b + j * S;
                v[j] = i < EF;
                d[j] = v[j] ? dstF[i] : 0;
                s[j] = v[j] ? srcF[i] : 0;
            }
#pragma unroll
            for (int j = 0; j < 8; j++) m[j] = mask_test(maskbits, s[j]);
#pragma unroll
            for (int j = 0; j < 8; j++) {
                if (v[j])
                    p[j] = m[j] ? atomicAdd(&curAF[d[j]], 1)
                                : (atomicSub(&curBF[d[j]], 1) - 1);
            }
#pragma unroll
            for (int j = 0; j < 8; j++)
                if (v[j]) csrF[p[j]] = s[j] | (m[j] ? 0x80000000 : 0);
        }
    } else {
        for (int b = t; b < EP; b += 8 * S) {
            int s[8], d[8], p[8]; bool v[8];
#pragma unroll
            for (int j = 0; j < 8; j++) {
                int i = b + j * S;
                v[j] = i < EP;
                d[j] = v[j] ? dstP[i] : 0;
                s[j] = v[j] ? srcP[i] : 0;
            }
#pragma unroll
            for (int j = 0; j < 8; j++)
                if (v[j]) p[j] = atomicAdd(&curAP[d[j]], 1);
#pragma unroll
            for (int j = 0; j < 8; j++)
                if (v[j]) csrP[p[j]] = s[j];
        }
    }
}

// ---------------- GEMM: y[node] = dinv[node] * (X[row] @ W), f32x2 packed ----------------
template <int REMAP>
__global__ __launch_bounds__(256) void gemm_kernel(
    const float* __restrict__ X, const float* __restrict__ W, int M,
    const int* __restrict__ off, const int* __restrict__ remap,
    float* __restrict__ y)
{
    __shared__ __align__(16) float AsT[32][66];
    __shared__ __align__(16) float Bs[32][128];
    int tid = threadIdx.x;
    int lane = tid & 31;
    int ty = tid >> 5;
    int rowBase = blockIdx.x * 64;

    unsigned long long acc[4][4];
#pragma unroll
    for (int rp = 0; rp < 4; rp++)
#pragma unroll
        for (int c = 0; c < 4; c++) acc[rp][c] = 0ull;

    for (int k0 = 0; k0 < 128; k0 += 32) {
#pragma unroll
        for (int s = 0; s < 2; s++) {
            int idx = tid * 2 + s;
            int r = idx >> 3;
            int c4 = idx & 7;
            float4 v = make_float4(0.f, 0.f, 0.f, 0.f);
            int grow = rowBase + r;
            if (grow < M) v = *(const float4*)(X + (size_t)grow * 128 + k0 + c4 * 4);
            AsT[c4 * 4 + 0][r] = v.x;
            AsT[c4 * 4 + 1][r] = v.y;
            AsT[c4 * 4 + 2][r] = v.z;
            AsT[c4 * 4 + 3][r] = v.w;
        }
#pragma unroll
        for (int s = 0; s < 4; s++) {
            int idx = tid * 4 + s;
            int r = idx >> 5;
            int c4 = idx & 31;
            *(float4*)&Bs[r][c4 * 4] = *(const float4*)(W + (size_t)(k0 + r) * 128 + c4 * 4);
        }
        __syncthreads();
#pragma unroll
        for (int k = 0; k < 32; k++) {
            unsigned long long a0 = *(const unsigned long long*)&AsT[k][ty * 8 + 0];
            unsigned long long a1 = *(const unsigned long long*)&AsT[k][ty * 8 + 2];
            unsigned long long a2 = *(const unsigned long long*)&AsT[k][ty * 8 + 4];
            unsigned long long a3 = *(const unsigned long long*)&AsT[k][ty * 8 + 6];
            float4 b = *(float4*)&Bs[k][lane * 4];
            unsigned long long bx, by, bz, bw;
            PACK2(bx, b.x, b.x);
            PACK2(by, b.y, b.y);
            PACK2(bz, b.z, b.z);
            PACK2(bw, b.w, b.w);
            FMA2(acc[0][0], a0, bx); FMA2(acc[0][1], a0, by);
            FMA2(acc[0][2], a0, bz); FMA2(acc[0][3], a0, bw);
            FMA2(acc[1][0], a1, bx); FMA2(acc[1][1], a1, by);
            FMA2(acc[1][2], a1, bz); FMA2(acc[1][3], a1, bw);
            FMA2(acc[2][0], a2, bx); FMA2(acc[2][1], a2, by);
            FMA2(acc[2][2], a2, bz); FMA2(acc[2][3], a2, bw);
            FMA2(acc[3][0], a3, bx); FMA2(acc[3][1], a3, by);
            FMA2(acc[3][2], a3, bz); FMA2(acc[3][3], a3, bw);
        }
        __syncthreads();
    }

#pragma unroll
    for (int rp = 0; rp < 4; rp++) {
        float lo0, hi0, lo1, hi1, lo2, hi2, lo3, hi3;
        UNPACK2(lo0, hi0, acc[rp][0]);
        UNPACK2(lo1, hi1, acc[rp][1]);
        UNPACK2(lo2, hi2, acc[rp][2]);
        UNPACK2(lo3, hi3, acc[rp][3]);
        int r0 = rowBase + ty * 8 + rp * 2;
        if (r0 < M) {
            int node = REMAP ? remap[r0] : r0;
            float s = rsqrtf((float)(off[node + 1] - off[node] + 1));
            float4 v = make_float4(lo0 * s, lo1 * s, lo2 * s, lo3 * s);
            *(float4*)(y + (size_t)node * 128 + lane * 4) = v;
        }
        if (r0 + 1 < M) {
            int node = REMAP ? remap[r0 + 1] : (r0 + 1);
            float s = rsqrtf((float)(off[node + 1] - off[node] + 1));
            float4 v = make_float4(hi0 * s, hi1 * s, hi2 * s, hi3 * s);
            *(float4*)(y + (size_t)node * 128 + lane * 4) = v;
        }
    }
}

// ---------------- fused gather + finalize ----------------
// out[d] = elu( dinv[d] * ( sum_{s in CSR[d]} y[s] + y[d] ) + b ),  dinv = rsqrt(deg+1)
// MODE 0: plain indices (pool). MODE 1: strip bit31 (full, all edges).
// MODE 2: kept edges are a compacted flagged prefix -> break at first unflagged;
//         self term gated by mask bit (conv1).
__device__ __forceinline__ float elu1(float x) {
    return x > 0.f ? x : expm1f(x);
}

template <int MODE>
__global__ __launch_bounds__(256) void gather_kernel(
    const int* __restrict__ off, const int* __restrict__ csr,
    const float* __restrict__ y, const float* __restrict__ b,
    float* __restrict__ out, int n, const unsigned int* __restrict__ maskbits)
{
    int lane = threadIdx.x & 31;
    int node = (blockIdx.x * blockDim.x + threadIdx.x) >> 5;
    if (node >= n) return;
    int e0 = __ldg(&off[node]);
    int e1 = __ldg(&off[node + 1]);
    const float* yl = y + lane * 4;

    float4 a0 = make_float4(0.f, 0.f, 0.f, 0.f);
    float4 a1 = make_float4(0.f, 0.f, 0.f, 0.f);
    float4 a2 = make_float4(0.f, 0.f, 0.f, 0.f);
    float4 a3 = make_float4(0.f, 0.f, 0.f, 0.f);

    bool selfOk = (MODE == 2) ? (mask_test(maskbits, node) != 0) : true;
    if (selfOk) a0 = *(const float4*)(yl + (size_t)node * 128);

    int e = e0;
    if (MODE == 2) {
        for (; e + 2 <= e1; e += 2) {
            int sA = __ldg(&csr[e]);
            int sB = __ldg(&csr[e + 1]);
            if (sA >= 0) goto done;
            {
                float4 vA = *(const float4*)(yl + (size_t)(sA & 0x7fffffff) * 128);
                a0.x += vA.x; a0.y += vA.y; a0.z += vA.z; a0.w += vA.w;
            }
            if (sB >= 0) goto done;
            {
                float4 vB = *(const float4*)(yl + (size_t)(sB & 0x7fffffff) * 128);
                a1.x += vB.x; a1.y += vB.y; a1.z += vB.z; a1.w += vB.w;
            }
        }
        if (e < e1) {
            int sA = __ldg(&csr[e]);
            if (sA < 0) {
                float4 vA = *(const float4*)(yl + (size_t)(sA & 0x7fffffff) * 128);
                a0.x += vA.x; a0.y += vA.y; a0.z += vA.z; a0.w += vA.w;
            }
        }
        done: ;
    } else {
        for (; e + 4 <= e1; e += 4) {
            int s0 = __ldg(&csr[e]);
            int s1 = __ldg(&csr[e + 1]);
            int s2 = __ldg(&csr[e + 2]);
            int s3 = __ldg(&csr[e + 3]);
            if (MODE == 1) {
                s0 &= 0x7fffffff; s1 &= 0x7fffffff;
                s2 &= 0x7fffffff; s3 &= 0x7fffffff;
            }
            float4 v0 = *(const float4*)(yl + (size_t)s0 * 128);
            float4 v1 = *(const float4*)(yl + (size_t)s1 * 128);
            float4 v2 = *(const float4*)(yl + (size_t)s2 * 128);
            float4 v3 = *(const float4*)(yl + (size_t)s3 * 128);
            a0.x += v0.x; a0.y += v0.y; a0.z += v0.z; a0.w += v0.w;
            a1.x += v1.x; a1.y += v1.y; a1.z += v1.z; a1.w += v1.w;
            a2.x += v2.x; a2.y += v2.y; a2.z += v2.z; a2.w += v2.w;
            a3.x += v3.x; a3.y += v3.y; a3.z += v3.z; a3.w += v3.w;
        }
        for (; e < e1; e++) {
            int s = __ldg(&csr[e]);
            if (MODE == 1) s &= 0x7fffffff;
            float4 v = *(const float4*)(yl + (size_t)s * 128);
            a0.x += v.x; a0.y += v.y; a0.z += v.z; a0.w += v.w;
        }
    }
    a0.x += a1.x + a2.x + a3.x;
    a0.y += a1.y + a2.y + a3.y;
    a0.z += a1.z + a2.z + a3.z;
    a0.w += a1.w + a2.w + a3.w;

    float s = rsqrtf((float)(e1 - e0 + 1));
    float4 bb = *(const float4*)(b + lane * 4);
    float4 o;
    o.x = elu1(fmaf(s, a0.x, bb.x));
    o.y = elu1(fmaf(s, a0.y, bb.y));
    o.z = elu1(fmaf(s, a0.z, bb.z));
    o.w = elu1(fmaf(s, a0.w, bb.w));
    *(float4*)(out + (size_t)node * 128 + lane * 4) = o;
}

// ---------------- launch (single stream; DAG parallelism doesn't pay here) ----------------
extern "C" void kernel_launch(void* const* d_in, const int* in_sizes, int n_in,
                              void* d_out, int out_size)
{
    const int* ei   = (const int*)d_in[1];
    const float* px = (const float*)d_in[2];
    const int* pei  = (const int*)d_in[3];
    const int* up   = (const int*)d_in[4];
    const float* W0 = (const float*)d_in[5];
    const float* b0 = (const float*)d_in[6];
    const float* W1 = (const float*)d_in[7];
    const float* b1 = (const float*)d_in[8];
    const float* W2 = (const float*)d_in[9];
    const float* b2 = (const float*)d_in[10];
    float* out = (float*)d_out;

    int nf = in_sizes[0] / DD;
    int ef = in_sizes[1] / 2;
    int np = in_sizes[2] / DD;
    int ep = in_sizes[3] / 2;

    float *ypool, *h, *y, *xf1;
    int *degp, *degf, *offf, *offp, *curfA, *curfB, *curp;
    int *csrf, *csrp, *sumsF, *sumsP;
    unsigned int *maskbits;
    cudaGetSymbolAddress((void**)&ypool,    d_ypool);
    cudaGetSymbolAddress((void**)&h,        d_h);
    cudaGetSymbolAddress((void**)&y,        d_y);
    cudaGetSymbolAddress((void**)&xf1,      d_xf1);
    cudaGetSymbolAddress((void**)&degp,     d_degp);
    cudaGetSymbolAddress((void**)&degf,     d_degf);
    cudaGetSymbolAddress((void**)&offf,     d_offf);
    cudaGetSymbolAddress((void**)&offp,     d_offp);
    cudaGetSymbolAddress((void**)&curfA,    d_curfA);
    cudaGetSymbolAddress((void**)&curfB,    d_curfB);
    cudaGetSymbolAddress((void**)&curp,     d_curp);
    cudaGetSymbolAddress((void**)&csrf,     d_csrf);
    cudaGetSymbolAddress((void**)&csrp,     d_csrp);
    cudaGetSymbolAddress((void**)&maskbits, d_maskbits);
    cudaGetSymbolAddress((void**)&sumsF,    d_sumsF);
    cudaGetSymbolAddress((void**)&sumsP,    d_sumsP);

    const int T = 256;
    auto cdiv = [](int a, int b) { return (a + b - 1) / b; };

    // only the degree arrays need zeroing each replay (maskbits is idempotent:
    // the same bits are OR'd every run).
    cudaMemsetAsync(degf, 0, nf * sizeof(int), 0);
    cudaMemsetAsync(degp, 0, np * sizeof(int), 0);

    // degrees (both graphs, 8-wide MLP) + mask bits in one launch
    degmask_kernel<<<dim3(cdiv(ef, T * 8), 3), T>>>(ei + ef, ef, degf,
                                                    pei + ep, ep, degp,
                                                    up, np, maskbits);

    // 2-kernel parallel exclusive scans; scan_p3 also emits CSR cursors
    scan_p1<<<dim3(NBF, 2), 1024>>>(degf, nf, sumsF, degp, np, sumsP);
    scan_p3<<<dim3(NBF, 2), 1024>>>(degf, nf, sumsF, offf, curfA, curfB,
                                    degp, np, sumsP, offp, curp);

    // CSR build (8-wide MLP; full graph: kept edges compacted to flagged prefix)
    csr_kernel<<<dim3(cdiv(ef, T * 8), 2), T>>>(ei, ei + ef, ef, curfA, curfB, csrf,
                                                maskbits,
                                                pei, pei + ep, ep, curp, csrp);

    // conv0 (pooled graph)
    gemm_kernel<0><<<cdiv(np, 64), 256>>>(px, W0, np, offp, nullptr, ypool);
    gather_kernel<0><<<cdiv(np * 32, T), T>>>(offp, csrp, ypool, b0, h, np, nullptr);

    // conv1 (full graph; GEMM only over 12.5k kept rows; gather reads kept prefix only)
    gemm_kernel<1><<<cdiv(np, 64), 256>>>(h, W1, np, offf, up, y);
    gather_kernel<2><<<cdiv(nf * 32, T), T>>>(offf, csrf, y, b1, xf1, nf, maskbits);

    // conv2 (full graph, dense; gemm overwrites all of y)
    gemm_kernel<0><<<cdiv(nf, 64), 256>>>(xf1, W2, nf, offf, nullptr, y);
    gather_kernel<1><<<cdiv(nf * 32, T), T>>>(offf, csrf, y, b2, out, nf, nullptr);
}

// round 17
// speedup vs baseline: 1.0554x; 1.0332x over previous
#include <cuda_runtime.h>
#include <cuda_fp16.h>
#include <math.h>

#define NFULL 50000
#define NPOOL 12500
#define EFULL 600000
#define EPOOL 150000
#define DD    128
#define NBF   ((NFULL + 1023) / 1024)   // 49
#define NBP   ((NPOOL + 1023) / 1024)   // 13
#define MBW   ((NFULL + 31) / 32)       // mask bit-words

// ---------------- device scratch (no allocation allowed) ----------------
__device__ __half d_ypool[NPOOL * DD];
__device__ float  d_h[NPOOL * DD];
__device__ __half d_y[NFULL * DD];
__device__ float  d_xf1[NFULL * DD];
__device__ int    d_degp[NPOOL];
__device__ int    d_degf[NFULL];
__device__ int    d_offf[NFULL + 1];
__device__ int    d_offp[NPOOL + 1];
__device__ int    d_curfA[NFULL];   // front cursor (kept edges)
__device__ int    d_curfB[NFULL];   // back cursor (unkept edges)
__device__ int    d_curp[NPOOL];
__device__ int    d_csrf[EFULL];
__device__ int    d_csrp[EPOOL];
__device__ unsigned int d_maskbits[MBW];
__device__ int    d_sumsF[64];
__device__ int    d_sumsP[64];

// ---------------- packed f32x2 asm ----------------
#define FMA2(acc, a, b) \
    asm("fma.rn.f32x2 %0, %1, %2, %0;" : "+l"(acc) : "l"(a), "l"(b))
#define PACK2(out, lo, hi) \
    asm("mov.b64 %0, {%1, %2};" : "=l"(out) : "f"(lo), "f"(hi))
#define UNPACK2(lo, hi, in) \
    asm("mov.b64 {%0, %1}, %2;" : "=f"(lo), "=f"(hi) : "l"(in))

__device__ __forceinline__ int mask_test(const unsigned int* __restrict__ mb, int i) {
    return (__ldg(&mb[i >> 5]) >> (i & 31)) & 1;
}

// load 4 halfs (8B) and accumulate into float4
__device__ __forceinline__ void acc_half4(float4& a, const __half* p) {
    uint2 u = *(const uint2*)p;
    __half2 h01 = *(__half2*)&u.x;
    __half2 h23 = *(__half2*)&u.y;
    float2 f01 = __half22float2(h01);
    float2 f23 = __half22float2(h23);
    a.x += f01.x; a.y += f01.y; a.z += f23.x; a.w += f23.y;
}

// ---------------- degree + mask kernel (8-wide MLP) ----------------
// blockIdx.y: 0 = full-graph degrees, 1 = pooled degrees, 2 = mask bits
__global__ __launch_bounds__(256) void degmask_kernel(
    const int* __restrict__ dstF, int EF, int* __restrict__ degF,
    const int* __restrict__ dstP, int EP, int* __restrict__ degP,
    const int* __restrict__ remap, int nP, unsigned int* __restrict__ maskbits)
{
    int t = blockIdx.x * blockDim.x + threadIdx.x;
    int S = gridDim.x * blockDim.x;
    if (blockIdx.y == 0) {
        for (int b = t; b < EF; b += 8 * S) {
            int d[8]; bool v[8];
#pragma unroll
            for (int j = 0; j < 8; j++) {
                int i = b + j * S;
                v[j] = i < EF;
                d[j] = v[j] ? dstF[i] : 0;
            }
#pragma unroll
            for (int j = 0; j < 8; j++)
                if (v[j]) atomicAdd(&degF[d[j]], 1);
        }
    } else if (blockIdx.y == 1) {
        for (int b = t; b < EP; b += 8 * S) {
            int d[8]; bool v[8];
#pragma unroll
            for (int j = 0; j < 8; j++) {
                int i = b + j * S;
                v[j] = i < EP;
                d[j] = v[j] ? dstP[i] : 0;
            }
#pragma unroll
            for (int j = 0; j < 8; j++)
                if (v[j]) atomicAdd(&degP[d[j]], 1);
        }
    } else {
        for (int i = t; i < nP; i += S) {
            int node = remap[i];
            atomicOr(&maskbits[node >> 5], 1u << (node & 31));
        }
    }
}

// ---- 2-kernel parallel exclusive scan (both graphs batched via blockIdx.y) ----
__global__ __launch_bounds__(1024) void scan_p1(
    const int* __restrict__ degF, int nF, int* __restrict__ sumsF,
    const int* __restrict__ degP, int nP, int* __restrict__ sumsP)
{
    const int* deg = blockIdx.y ? degP : degF;
    int n = blockIdx.y ? nP : nF;
    int* sums = blockIdx.y ? sumsP : sumsF;
    int base = blockIdx.x * 1024;
    if (base >= n) return;
    int i = base + threadIdx.x;
    int v = (i < n) ? deg[i] : 0;
    __shared__ int ws[32];
    int lane = threadIdx.x & 31, wid = threadIdx.x >> 5;
#pragma unroll
    for (int d = 16; d > 0; d >>= 1) v += __shfl_down_sync(0xffffffffu, v, d);
    if (lane == 0) ws[wid] = v;
    __syncthreads();
    if (wid == 0) {
        int t = ws[lane];
#pragma unroll
        for (int d = 16; d > 0; d >>= 1) t += __shfl_down_sync(0xffffffffu, t, d);
        if (lane == 0) sums[blockIdx.x] = t;
    }
}

// each block reduces preceding block-sums itself, scans its 1024 elements,
// writes off[i], CSR cursor(s), and off[n] at the tail.
__global__ __launch_bounds__(1024) void scan_p3(
    const int* __restrict__ degF, int nF, const int* __restrict__ sumsF,
    int* __restrict__ offF, int* __restrict__ curAF, int* __restrict__ curBF,
    const int* __restrict__ degP, int nP, const int* __restrict__ sumsP,
    int* __restrict__ offP, int* __restrict__ curAP)
{
    const int* deg  = blockIdx.y ? degP  : degF;
    int n           = blockIdx.y ? nP    : nF;
    const int* sums = blockIdx.y ? sumsP : sumsF;
    int* off        = blockIdx.y ? offP  : offF;
    int* curA       = blockIdx.y ? curAP : curAF;
    int* curB       = blockIdx.y ? (int*)0 : curBF;
    int base = blockIdx.x * 1024;
    if (base >= n) return;

    __shared__ int ws[32];
    __shared__ int red2[2];
    __shared__ int sumbase_s;
    int tid = threadIdx.x;
    int lane = tid & 31, wid = tid >> 5;

    if (tid < 64) {
        int v = (tid < blockIdx.x) ? sums[tid] : 0;
#pragma unroll
        for (int d = 16; d > 0; d >>= 1) v += __shfl_down_sync(0xffffffffu, v, d);
        if (lane == 0) red2[wid] = v;
    }
    __syncthreads();
    if (tid == 0) sumbase_s = red2[0] + red2[1];
    __syncthreads();

    int i = base + tid;
    int v = (i < n) ? deg[i] : 0;
    int x = v;
#pragma unroll
    for (int d = 1; d < 32; d <<= 1) {
        int t = __shfl_up_sync(0xffffffffu, x, d);
        if (lane >= d) x += t;
    }
    if (lane == 31) ws[wid] = x;
    __syncthreads();
    if (wid == 0) {
        int w = ws[lane];
#pragma unroll
        for (int d = 1; d < 32; d <<= 1) {
            int t = __shfl_up_sync(0xffffffffu, w, d);
            if (lane >= d) w += t;
        }
        ws[lane] = w;
    }
    __syncthreads();
    int excl = (x - v) + (wid > 0 ? ws[wid - 1] : 0) + sumbase_s;
    if (i < n) {
        off[i]  = excl;
        curA[i] = excl;                    // front cursor
        if (curB) curB[i] = excl + v;      // back cursor (full graph only)
        if (i == n - 1) off[n] = excl + v;
    }
}

// ---------------- CSR build (batched, 4-wide MLP, bitmask) ----------------
// full graph: kept-source edges compacted to FRONT (bit31 set); unkept from back.
__global__ __launch_bounds__(256) void csr_kernel(
    const int* __restrict__ srcF, const int* __restrict__ dstF, int EF,
    int* __restrict__ curAF, int* __restrict__ curBF, int* __restrict__ csrF,
    const unsigned int* __restrict__ maskbits,
    const int* __restrict__ srcP, const int* __restrict__ dstP, int EP,
    int* __restrict__ curAP, int* __restrict__ csrP)
{
    int t = blockIdx.x * blockDim.x + threadIdx.x;
    int S = gridDim.x * blockDim.x;
    if (blockIdx.y == 0) {
        for (int b = t; b < EF; b += 4 * S) {
            int i1 = b + S, i2 = b + 2 * S, i3 = b + 3 * S;
            bool v1 = i1 < EF, v2 = i2 < EF, v3 = i3 < EF;
            int d0 = dstF[b],            s0 = srcF[b];
            int d1 = v1 ? dstF[i1] : 0,  s1 = v1 ? srcF[i1] : 0;
            int d2 = v2 ? dstF[i2] : 0,  s2 = v2 ? srcF[i2] : 0;
            int d3 = v3 ? dstF[i3] : 0,  s3 = v3 ? srcF[i3] : 0;
            int m0 = mask_test(maskbits, s0);
            int m1 = v1 ? mask_test(maskbits, s1) : 0;
            int m2 = v2 ? mask_test(maskbits, s2) : 0;
            int m3 = v3 ? mask_test(maskbits, s3) : 0;
            int p0 = m0 ? atomicAdd(&curAF[d0], 1) : (atomicSub(&curBF[d0], 1) - 1);
            int p1 = v1 ? (m1 ? atomicAdd(&curAF[d1], 1) : (atomicSub(&curBF[d1], 1) - 1)) : 0;
            int p2 = v2 ? (m2 ? atomicAdd(&curAF[d2], 1) : (atomicSub(&curBF[d2], 1) - 1)) : 0;
            int p3 = v3 ? (m3 ? atomicAdd(&curAF[d3], 1) : (atomicSub(&curBF[d3], 1) - 1)) : 0;
            csrF[p0] = s0 | (m0 ? 0x80000000 : 0);
            if (v1) csrF[p1] = s1 | (m1 ? 0x80000000 : 0);
            if (v2) csrF[p2] = s2 | (m2 ? 0x80000000 : 0);
            if (v3) csrF[p3] = s3 | (m3 ? 0x80000000 : 0);
        }
    } else {
        for (int b = t; b < EP; b += 4 * S) {
            int i1 = b + S, i2 = b + 2 * S, i3 = b + 3 * S;
            bool v1 = i1 < EP, v2 = i2 < EP, v3 = i3 < EP;
            int d0 = dstP[b],           s0 = srcP[b];
            int d1 = v1 ? dstP[i1] : 0, s1 = v1 ? srcP[i1] : 0;
            int d2 = v2 ? dstP[i2] : 0, s2 = v2 ? srcP[i2] : 0;
            int d3 = v3 ? dstP[i3] : 0, s3 = v3 ? srcP[i3] : 0;
            int p0 = atomicAdd(&curAP[d0], 1);
            int p1 = v1 ? atomicAdd(&curAP[d1], 1) : 0;
            int p2 = v2 ? atomicAdd(&curAP[d2], 1) : 0;
            int p3 = v3 ? atomicAdd(&curAP[d3], 1) : 0;
            csrP[p0] = s0;
            if (v1) csrP[p1] = s1;
            if (v2) csrP[p2] = s2;
            if (v3) csrP[p3] = s3;
        }
    }
}

// ---------------- GEMM: y[node] = half( dinv[node] * (X[row] @ W) ), f32x2 packed ----------------
template <int REMAP>
__global__ __launch_bounds__(256) void gemm_kernel(
    const float* __restrict__ X, const float* __restrict__ W, int M,
    const int* __restrict__ off, const int* __restrict__ remap,
    __half* __restrict__ y)
{
    __shared__ __align__(16) float AsT[32][66];
    __shared__ __align__(16) float Bs[32][128];
    int tid = threadIdx.x;
    int lane = tid & 31;
    int ty = tid >> 5;
    int rowBase = blockIdx.x * 64;

    unsigned long long acc[4][4];
#pragma unroll
    for (int rp = 0; rp < 4; rp++)
#pragma unroll
        for (int c = 0; c < 4; c++) acc[rp][c] = 0ull;

    for (int k0 = 0; k0 < 128; k0 += 32) {
#pragma unroll
        for (int s = 0; s < 2; s++) {
            int idx = tid * 2 + s;
            int r = idx >> 3;
            int c4 = idx & 7;
            float4 v = make_float4(0.f, 0.f, 0.f, 0.f);
            int grow = rowBase + r;
            if (grow < M) v = *(const float4*)(X + (size_t)grow * 128 + k0 + c4 * 4);
            AsT[c4 * 4 + 0][r] = v.x;
            AsT[c4 * 4 + 1][r] = v.y;
            AsT[c4 * 4 + 2][r] = v.z;
            AsT[c4 * 4 + 3][r] = v.w;
        }
#pragma unroll
        for (int s = 0; s < 4; s++) {
            int idx = tid * 4 + s;
            int r = idx >> 5;
            int c4 = idx & 31;
            *(float4*)&Bs[r][c4 * 4] = *(const float4*)(W + (size_t)(k0 + r) * 128 + c4 * 4);
        }
        __syncthreads();
#pragma unroll
        for (int k = 0; k < 32; k++) {
            unsigned long long a0 = *(const unsigned long long*)&AsT[k][ty * 8 + 0];
            unsigned long long a1 = *(const unsigned long long*)&AsT[k][ty * 8 + 2];
            unsigned long long a2 = *(const unsigned long long*)&AsT[k][ty * 8 + 4];
            unsigned long long a3 = *(const unsigned long long*)&AsT[k][ty * 8 + 6];
            float4 b = *(float4*)&Bs[k][lane * 4];
            unsigned long long bx, by, bz, bw;
            PACK2(bx, b.x, b.x);
            PACK2(by, b.y, b.y);
            PACK2(bz, b.z, b.z);
            PACK2(bw, b.w, b.w);
            FMA2(acc[0][0], a0, bx); FMA2(acc[0][1], a0, by);
            FMA2(acc[0][2], a0, bz); FMA2(acc[0][3], a0, bw);
            FMA2(acc[1][0], a1, bx); FMA2(acc[1][1], a1, by);
            FMA2(acc[1][2], a1, bz); FMA2(acc[1][3], a1, bw);
            FMA2(acc[2][0], a2, bx); FMA2(acc[2][1], a2, by);
            FMA2(acc[2][2], a2, bz); FMA2(acc[2][3], a2, bw);
            FMA2(acc[3][0], a3, bx); FMA2(acc[3][1], a3, by);
            FMA2(acc[3][2], a3, bz); FMA2(acc[3][3], a3, bw);
        }
        __syncthreads();
    }

#pragma unroll
    for (int rp = 0; rp < 4; rp++) {
        float lo0, hi0, lo1, hi1, lo2, hi2, lo3, hi3;
        UNPACK2(lo0, hi0, acc[rp][0]);
        UNPACK2(lo1, hi1, acc[rp][1]);
        UNPACK2(lo2, hi2, acc[rp][2]);
        UNPACK2(lo3, hi3, acc[rp][3]);
        int r0 = rowBase + ty * 8 + rp * 2;
        if (r0 < M) {
            int node = REMAP ? remap[r0] : r0;
            float s = rsqrtf((float)(off[node + 1] - off[node] + 1));
            __half2 p0 = __floats2half2_rn(lo0 * s, lo1 * s);
            __half2 p1 = __floats2half2_rn(lo2 * s, lo3 * s);
            uint2 u = make_uint2(*(unsigned*)&p0, *(unsigned*)&p1);
            *(uint2*)(y + (size_t)node * 128 + lane * 4) = u;
        }
        if (r0 + 1 < M) {
            int node = REMAP ? remap[r0 + 1] : (r0 + 1);
            float s = rsqrtf((float)(off[node + 1] - off[node] + 1));
            __half2 p0 = __floats2half2_rn(hi0 * s, hi1 * s);
            __half2 p1 = __floats2half2_rn(hi2 * s, hi3 * s);
            uint2 u = make_uint2(*(unsigned*)&p0, *(unsigned*)&p1);
            *(uint2*)(y + (size_t)node * 128 + lane * 4) = u;
        }
    }
}

// ---------------- fused gather + finalize ----------------
// out[d] = elu( dinv[d] * ( sum_{s in CSR[d]} y[s] + y[d] ) + b ),  dinv = rsqrt(deg+1)
// y is fp16 (prescaled by src dinv); accumulation in fp32.
// MODE 0: plain indices (pool). MODE 1: strip bit31 (full, all edges).
// MODE 2: kept edges are a compacted flagged prefix -> break at first unflagged;
//         self term gated by mask bit (conv1).
__device__ __forceinline__ float elu1(float x) {
    return x > 0.f ? x : expm1f(x);
}

template <int MODE>
__global__ __launch_bounds__(256) void gather_kernel(
    const int* __restrict__ off, const int* __restrict__ csr,
    const __half* __restrict__ y, const float* __restrict__ b,
    float* __restrict__ out, int n, const unsigned int* __restrict__ maskbits)
{
    int lane = threadIdx.x & 31;
    int node = (blockIdx.x * blockDim.x + threadIdx.x) >> 5;
    if (node >= n) return;
    int e0 = __ldg(&off[node]);
    int e1 = __ldg(&off[node + 1]);
    const __half* yl = y + lane * 4;

    float4 a0 = make_float4(0.f, 0.f, 0.f, 0.f);
    float4 a1 = make_float4(0.f, 0.f, 0.f, 0.f);
    float4 a2 = make_float4(0.f, 0.f, 0.f, 0.f);
    float4 a3 = make_float4(0.f, 0.f, 0.f, 0.f);

    bool selfOk = (MODE == 2) ? (mask_test(maskbits, node) != 0) : true;
    if (selfOk) acc_half4(a0, yl + (size_t)node * 128);

    int e = e0;
    if (MODE == 2) {
        for (; e + 2 <= e1; e += 2) {
            int sA = __ldg(&csr[e]);
            int sB = __ldg(&csr[e + 1]);
            if (sA >= 0) goto done;
            acc_half4(a0, yl + (size_t)(sA & 0x7fffffff) * 128);
            if (sB >= 0) goto done;
            acc_half4(a1, yl + (size_t)(sB & 0x7fffffff) * 128);
        }
        if (e < e1) {
            int sA = __ldg(&csr[e]);
            if (sA < 0) acc_half4(a0, yl + (size_t)(sA & 0x7fffffff) * 128);
        }
        done: ;
    } else {
        for (; e + 4 <= e1; e += 4) {
            int s0 = __ldg(&csr[e]);
            int s1 = __ldg(&csr[e + 1]);
            int s2 = __ldg(&csr[e + 2]);
            int s3 = __ldg(&csr[e + 3]);
            if (MODE == 1) {
                s0 &= 0x7fffffff; s1 &= 0x7fffffff;
                s2 &= 0x7fffffff; s3 &= 0x7fffffff;
            }
            acc_half4(a0, yl + (size_t)s0 * 128);
            acc_half4(a1, yl + (size_t)s1 * 128);
            acc_half4(a2, yl + (size_t)s2 * 128);
            acc_half4(a3, yl + (size_t)s3 * 128);
        }
        for (; e < e1; e++) {
            int s = __ldg(&csr[e]);
            if (MODE == 1) s &= 0x7fffffff;
            acc_half4(a0, yl + (size_t)s * 128);
        }
    }
    a0.x += a1.x + a2.x + a3.x;
    a0.y += a1.y + a2.y + a3.y;
    a0.z += a1.z + a2.z + a3.z;
    a0.w += a1.w + a2.w + a3.w;

    float s = rsqrtf((float)(e1 - e0 + 1));
    float4 bb = *(const float4*)(b + lane * 4);
    float4 o;
    o.x = elu1(fmaf(s, a0.x, bb.x));
    o.y = elu1(fmaf(s, a0.y, bb.y));
    o.z = elu1(fmaf(s, a0.z, bb.z));
    o.w = elu1(fmaf(s, a0.w, bb.w));
    *(float4*)(out + (size_t)node * 128 + lane * 4) = o;
}

// ---------------- launch (single stream) ----------------
extern "C" void kernel_launch(void* const* d_in, const int* in_sizes, int n_in,
                              void* d_out, int out_size)
{
    const int* ei   = (const int*)d_in[1];
    const float* px = (const float*)d_in[2];
    const int* pei  = (const int*)d_in[3];
    const int* up   = (const int*)d_in[4];
    const float* W0 = (const float*)d_in[5];
    const float* b0 = (const float*)d_in[6];
    const float* W1 = (const float*)d_in[7];
    const float* b1 = (const float*)d_in[8];
    const float* W2 = (const float*)d_in[9];
    const float* b2 = (const float*)d_in[10];
    float* out = (float*)d_out;

    int nf = in_sizes[0] / DD;
    int ef = in_sizes[1] / 2;
    int np = in_sizes[2] / DD;
    int ep = in_sizes[3] / 2;

    __half *ypool, *y;
    float *h, *xf1;
    int *degp, *degf, *offf, *offp, *curfA, *curfB, *curp;
    int *csrf, *csrp, *sumsF, *sumsP;
    unsigned int *maskbits;
    cudaGetSymbolAddress((void**)&ypool,    d_ypool);
    cudaGetSymbolAddress((void**)&h,        d_h);
    cudaGetSymbolAddress((void**)&y,        d_y);
    cudaGetSymbolAddress((void**)&xf1,      d_xf1);
    cudaGetSymbolAddress((void**)&degp,     d_degp);
    cudaGetSymbolAddress((void**)&degf,     d_degf);
    cudaGetSymbolAddress((void**)&offf,     d_offf);
    cudaGetSymbolAddress((void**)&offp,     d_offp);
    cudaGetSymbolAddress((void**)&curfA,    d_curfA);
    cudaGetSymbolAddress((void**)&curfB,    d_curfB);
    cudaGetSymbolAddress((void**)&curp,     d_curp);
    cudaGetSymbolAddress((void**)&csrf,     d_csrf);
    cudaGetSymbolAddress((void**)&csrp,     d_csrp);
    cudaGetSymbolAddress((void**)&maskbits, d_maskbits);
    cudaGetSymbolAddress((void**)&sumsF,    d_sumsF);
    cudaGetSymbolAddress((void**)&sumsP,    d_sumsP);

    const int T = 256;
    auto cdiv = [](int a, int b) { return (a + b - 1) / b; };

    // only the degree arrays need zeroing each replay (maskbits is idempotent:
    // the same bits are OR'd every run).
    cudaMemsetAsync(degf, 0, nf * sizeof(int), 0);
    cudaMemsetAsync(degp, 0, np * sizeof(int), 0);

    // degrees (both graphs, 8-wide MLP) + mask bits in one launch
    degmask_kernel<<<dim3(cdiv(ef, T * 8), 3), T>>>(ei + ef, ef, degf,
                                                    pei + ep, ep, degp,
                                                    up, np, maskbits);

    // 2-kernel parallel exclusive scans; scan_p3 also emits CSR cursors
    scan_p1<<<dim3(NBF, 2), 1024>>>(degf, nf, sumsF, degp, np, sumsP);
    scan_p3<<<dim3(NBF, 2), 1024>>>(degf, nf, sumsF, offf, curfA, curfB,
                                    degp, np, sumsP, offp, curp);

    // CSR build (4-wide MLP + bitmask; kept edges compacted to flagged prefix)
    csr_kernel<<<dim3(cdiv(ef, T * 4), 2), T>>>(ei, ei + ef, ef, curfA, curfB, csrf,
                                                maskbits,
                                                pei, pei + ep, ep, curp, csrp);

    // conv0 (pooled graph)
    gemm_kernel<0><<<cdiv(np, 64), 256>>>(px, W0, np, offp, nullptr, ypool);
    gather_kernel<0><<<cdiv(np * 32, T), T>>>(offp, csrp, ypool, b0, h, np, nullptr);

    // conv1 (full graph; GEMM only over 12.5k kept rows; gather reads kept prefix only)
    gemm_kernel<1><<<cdiv(np, 64), 256>>>(h, W1, np, offf, up, y);
    gather_kernel<2><<<cdiv(nf * 32, T), T>>>(offf, csrf, y, b1, xf1, nf, maskbits);

    // conv2 (full graph, dense; gemm overwrites all of y)
    gemm_kernel<0><<<cdiv(nf, 64), 256>>>(xf1, W2, nf, offf, nullptr, y);
    gather_kernel<1><<<cdiv(nf * 32, T), T>>>(offf, csrf, y, b2, out, nf, nullptr);
}